// round 11
// baseline (speedup 1.0000x reference)
#include <cuda_runtime.h>
#include <cuda_bf16.h>
#include <cstdint>

#define D 64
#define K 32
#define VOCAB_MAX 100000

// Scratch (alloc-free rule): bf16 P/Q
__device__ unsigned short g_Pb[(size_t)VOCAB_MAX * D];   // bf16(u2e @ W1a)
__device__ unsigned short g_Qb[(size_t)VOCAB_MAX * D];   // bf16(u2e @ W1b + b1)
__device__ int g_flags[1];   // [0] != 0 -> mask buffer is bytes (else 32-bit words)

// ======================= helpers =======================
__device__ __forceinline__ uint32_t smem_to_u32(const void* p) {
    uint32_t a;
    asm("{ .reg .u64 t; cvta.to.shared.u64 t, %1; cvt.u32.u64 %0, t; }" : "=r"(a) : "l"(p));
    return a;
}
#define CVT_BF16X2_F32(result, a, b) \
    asm("cvt.rn.satfinite.bf16x2.f32 %0, %1, %2;" : "=r"(result) : "f"(b), "f"(a))
#define ADD_BF16X2(r, a, b) \
    asm("add.bf16x2 %0, %1, %2;" : "=r"(r) : "r"(a), "r"(b))
#define MAX_BF16X2(r, a, b) \
    asm("max.bf16x2 %0, %1, %2;" : "=r"(r) : "r"(a), "r"(b))

#define LDMATRIX_X4(r0, r1, r2, r3, addr) \
    asm volatile("ldmatrix.sync.aligned.m8n8.x4.shared.b16 {%0,%1,%2,%3}, [%4];" \
        : "=r"(r0), "=r"(r1), "=r"(r2), "=r"(r3) : "r"(addr))
#define LDMATRIX_X4_TRANS(r0, r1, r2, r3, addr) \
    asm volatile("ldmatrix.sync.aligned.m8n8.x4.trans.shared.b16 {%0,%1,%2,%3}, [%4];" \
        : "=r"(r0), "=r"(r1), "=r"(r2), "=r"(r3) : "r"(addr))

// D (f32) += A (bf16) x B (bf16); C==D accumulate in place
#define MMA16816(d0, d1, d2, d3, a0, a1, a2, a3, b0, b1) \
    asm volatile("mma.sync.aligned.m16n8k16.row.col.f32.bf16.bf16.f32 " \
        "{%0,%1,%2,%3}, {%4,%5,%6,%7}, {%8,%9}, {%0,%1,%2,%3};" \
        : "+f"(d0), "+f"(d1), "+f"(d2), "+f"(d3) \
        : "r"(a0), "r"(a1), "r"(a2), "r"(a3), "r"(b0), "r"(b1))

#define CP_ASYNC16(dst_u32, src_ptr) \
    asm volatile("cp.async.cg.shared.global [%0], [%1], 16;" \
        :: "r"(dst_u32), "l"(src_ptr) : "memory")
#define CP_COMMIT()  asm volatile("cp.async.commit_group;" ::: "memory")
#define CP_WAIT1()   asm volatile("cp.async.wait_group 1;" ::: "memory")
#define CP_WAIT0()   asm volatile("cp.async.wait_group 0;" ::: "memory")

// A-tile SMEM: row stride 72 bf16 (144B) -> conflict-free ldmatrix
#define ASTRIDE_B 144

// ======================= prep: P/Q (bf16 out) + mask dtype scan =======================
__global__ __launch_bounds__(128) void prep_mma_kernel(const float* __restrict__ u2e,
                                                       const float* __restrict__ W1,
                                                       const float* __restrict__ b1,
                                                       int V,
                                                       const unsigned int* __restrict__ mbuf,
                                                       int n_words) {
    __shared__ __align__(16) unsigned char sA[4][32 * ASTRIDE_B];
    __shared__ __align__(16) unsigned char sW[128 * ASTRIDE_B];  // W1 [128 k][64 n] bf16
    __shared__ float sb1[64];
    int tid = threadIdx.x, warp = tid >> 5, lane = tid & 31;

    // ---- mask dtype scan (byte vs word); 0->1 idempotent across graph replays ----
    {
        int byte_mode = 0;
        for (int i = blockIdx.x * blockDim.x + tid; i < n_words; i += gridDim.x * blockDim.x) {
            unsigned int w = mbuf[i];
            if (w != 0u && w != 1u && w != 0x3f800000u) { byte_mode = 1; break; }
        }
        if (byte_mode) atomicOr(&g_flags[0], 1);
    }

    // ---- stage W1 (bf16, padded rows) ----
    for (int p = tid; p < 128 * 32; p += 128) {
        int r = p >> 5, cp = p & 31;
        uint32_t v;
        CVT_BF16X2_F32(v, W1[(size_t)r * 64 + 2 * cp], W1[(size_t)r * 64 + 2 * cp + 1]);
        *(uint32_t*)(sW + r * ASTRIDE_B + cp * 4) = v;
    }
    if (tid < 64) sb1[tid] = b1[tid];
    __syncthreads();

    int v0 = (blockIdx.x * 4 + warp) * 32;
    int vr = v0 + lane;
    int vc = (vr < V) ? vr : (V - 1);

    // Stage this lane's u2e row as bf16 into the warp's A tile
    {
        const float4* row = (const float4*)(u2e + (size_t)vc * D);
        unsigned char* dst = sA[warp] + lane * ASTRIDE_B;
#pragma unroll
        for (int i = 0; i < 8; i++) {
            float4 f0 = row[2 * i], f1 = row[2 * i + 1];
            uint4 w;
            CVT_BF16X2_F32(w.x, f0.x, f0.y);
            CVT_BF16X2_F32(w.y, f0.z, f0.w);
            CVT_BF16X2_F32(w.z, f1.x, f1.y);
            CVT_BF16X2_F32(w.w, f1.z, f1.w);
            *(uint4*)(dst + i * 16) = w;
        }
    }
    __syncwarp();

    uint32_t af[2][4][4];
    uint32_t a_base = smem_to_u32(sA[warp]);
#pragma unroll
    for (int mt = 0; mt < 2; mt++)
#pragma unroll
        for (int ks = 0; ks < 4; ks++) {
            uint32_t addr = a_base + (mt * 16 + (lane & 15)) * ASTRIDE_B + ks * 32 + (lane >> 4) * 16;
            LDMATRIX_X4(af[mt][ks][0], af[mt][ks][1], af[mt][ks][2], af[mt][ks][3], addr);
        }

    uint32_t w_base = smem_to_u32(sW);
    int j0 = 2 * (lane & 3);
    int r0 = lane >> 2;

#pragma unroll
    for (int half = 0; half < 2; half++) {
        unsigned short* gOut = half ? g_Qb : g_Pb;
#pragma unroll
        for (int nt = 0; nt < 8; nt++) {
            uint32_t b[4][2];
            {
                uint32_t r0b, r1b, r2b, r3b;
                uint32_t addr = w_base + (half * 64 + lane) * ASTRIDE_B + nt * 16;
                LDMATRIX_X4_TRANS(r0b, r1b, r2b, r3b, addr);
                b[0][0] = r0b; b[0][1] = r1b; b[1][0] = r2b; b[1][1] = r3b;
                addr = w_base + (half * 64 + 32 + lane) * ASTRIDE_B + nt * 16;
                LDMATRIX_X4_TRANS(r0b, r1b, r2b, r3b, addr);
                b[2][0] = r0b; b[2][1] = r1b; b[3][0] = r2b; b[3][1] = r3b;
            }
            int j = nt * 8 + j0;
            float init0 = half ? sb1[j] : 0.f;
            float init1 = half ? sb1[j + 1] : 0.f;
#pragma unroll
            for (int mt = 0; mt < 2; mt++) {
                float d0 = init0, d1 = init1, d2 = init0, d3 = init1;
#pragma unroll
                for (int ks = 0; ks < 4; ks++)
                    MMA16816(d0, d1, d2, d3,
                             af[mt][ks][0], af[mt][ks][1], af[mt][ks][2], af[mt][ks][3],
                             b[ks][0], b[ks][1]);
                int ra = v0 + mt * 16 + r0;
                int rb = ra + 8;
                uint32_t wlo, whi;
                CVT_BF16X2_F32(wlo, d0, d1);
                CVT_BF16X2_F32(whi, d2, d3);
                if (ra < V) *(uint32_t*)(gOut + (size_t)ra * D + j) = wlo;
                if (rb < V) *(uint32_t*)(gOut + (size_t)rb * D + j) = whi;
            }
        }
    }
}

// ======================= agg: persistent; cp.async double-buffered gathers ==============
// Raw P rows prefetched to SMEM via cp.async (no register cost); Q applied in fragment
// domain (broadcast LDS); B (W2) fragments FULLY hoisted to registers.
__global__ __launch_bounds__(128, 4) void agg_mma_kernel(
    const float* __restrict__ u2e,
    const float* __restrict__ W2, const float* __restrict__ b2,
    const float* __restrict__ W3, const float* __restrict__ b3,
    const int* __restrict__ nodes, const int* __restrict__ neigh_idx,
    const void* __restrict__ maskbuf,
    float* __restrict__ out, int n_nodes) {
    __shared__ __align__(16) unsigned char sA[4][2][32 * ASTRIDE_B];  // per-warp double-buffered raw-P
    __shared__ __align__(16) unsigned char sQ[4][2][128];             // per-warp staged Q row (bf16)
    __shared__ __align__(16) unsigned char sW2[64 * ASTRIDE_B];       // W2 staging (bf16)
    __shared__ float sb2[64];
    __shared__ float sW3[64];
    int tid = threadIdx.x, warp = tid >> 5, lane = tid & 31;

    for (int p = tid; p < 64 * 32; p += 128) {
        int r = p >> 5, cp = p & 31;
        uint32_t v;
        CVT_BF16X2_F32(v, W2[(size_t)r * 64 + 2 * cp], W2[(size_t)r * 64 + 2 * cp + 1]);
        *(uint32_t*)(sW2 + r * ASTRIDE_B + cp * 4) = v;
    }
    if (tid < 64) { sb2[tid] = b2[tid]; sW3[tid] = W3[tid]; }
    __syncthreads();

    // ---- full B-fragment hoist (loop-invariant W2): 64 registers ----
    uint32_t bf[8][4][2];
    {
        uint32_t w_base = smem_to_u32(sW2);
#pragma unroll
        for (int nt = 0; nt < 8; nt++) {
            uint32_t r0b, r1b, r2b, r3b;
            uint32_t addr = w_base + lane * ASTRIDE_B + nt * 16;
            LDMATRIX_X4_TRANS(r0b, r1b, r2b, r3b, addr);
            bf[nt][0][0] = r0b; bf[nt][0][1] = r1b; bf[nt][1][0] = r2b; bf[nt][1][1] = r3b;
            addr = w_base + (32 + lane) * ASTRIDE_B + nt * 16;
            LDMATRIX_X4_TRANS(r0b, r1b, r2b, r3b, addr);
            bf[nt][2][0] = r0b; bf[nt][2][1] = r1b; bf[nt][3][0] = r2b; bf[nt][3][1] = r3b;
        }
    }

    const float b3f = b3[0];
    const int byte_mode = g_flags[0];
    const int j0l = 2 * (lane & 3);
    const int seg = lane & 7;        // 16B segment within a 128B bf16 row
    const int rsub = lane >> 3;      // 0..3 (row within a 4-row load group)
    const int erow_sub = lane >> 4;  // 0..1 (row parity for epilogue)
    const int ecol = (lane & 15) * 4;
    uint32_t abuf[2] = { smem_to_u32(&sA[warp][0][0]), smem_to_u32(&sA[warp][1][0]) };
    uint32_t qbuf[2] = { smem_to_u32(&sQ[warp][0][0]), smem_to_u32(&sQ[warp][1][0]) };
    int wg = blockIdx.x * 4 + warp;
    int stride = gridDim.x * 4;

    if (wg >= n_nodes) return;

    // ---- prologue: prefetch first node's P rows + Q row into buffer 0 ----
    int idx, m;
    {
        idx = neigh_idx[(size_t)wg * K + lane];
        if (byte_mode)
            m = ((const unsigned char*)maskbuf)[(size_t)wg * K + lane] != 0;
        else
            m = ((const unsigned int*)maskbuf)[(size_t)wg * K + lane] != 0u;
        int node = nodes[wg];
#pragma unroll
        for (int it = 0; it < 8; it++) {
            int row = it * 4 + rsub;
            int ridx = __shfl_sync(0xffffffffu, idx, row);
            CP_ASYNC16(abuf[0] + row * ASTRIDE_B + seg * 16,
                       (const void*)(g_Pb + (size_t)ridx * D + seg * 8));
        }
        if (rsub == 0)
            CP_ASYNC16(qbuf[0] + seg * 16, (const void*)(g_Qb + (size_t)node * D + seg * 8));
        CP_COMMIT();
    }

    int cur = 0;
    for (int n = wg; n < n_nodes; n += stride) {
        // ---- prefetch next node's front-end into the other buffer ----
        int n2 = n + stride;
        int nc2 = (n2 < n_nodes) ? n2 : n;
        int idx2 = neigh_idx[(size_t)nc2 * K + lane];
        int m2;
        if (byte_mode)
            m2 = ((const unsigned char*)maskbuf)[(size_t)nc2 * K + lane] != 0;
        else
            m2 = ((const unsigned int*)maskbuf)[(size_t)nc2 * K + lane] != 0u;
        int node2 = nodes[nc2];
        int nxt = cur ^ 1;
#pragma unroll
        for (int it = 0; it < 8; it++) {
            int row = it * 4 + rsub;
            int ridx = __shfl_sync(0xffffffffu, idx2, row);
            CP_ASYNC16(abuf[nxt] + row * ASTRIDE_B + seg * 16,
                       (const void*)(g_Pb + (size_t)ridx * D + seg * 8));
        }
        if (rsub == 0)
            CP_ASYNC16(qbuf[nxt] + seg * 16, (const void*)(g_Qb + (size_t)node2 * D + seg * 8));
        CP_COMMIT();

        // ---- wait for current buffer (1 group = the one just issued may remain) ----
        CP_WAIT1();
        __syncwarp();

        // ---- Q values for fragment domain: qv[ks][h] = Q[cols (lane&3)*2 + ks*16 + h*8] ----
        uint32_t qv[4][2];
#pragma unroll
        for (int ks = 0; ks < 4; ks++) {
#pragma unroll
            for (int h = 0; h < 2; h++) {
                uint32_t off = qbuf[cur] + (lane & 3) * 4 + ks * 32 + h * 16;
                asm volatile("ld.shared.b32 %0, [%1];" : "=r"(qv[ks][h]) : "r"(off));
            }
        }

        // ---- A fragments: ldmatrix raw P, then fuse +Q and relu in registers ----
        uint32_t af[2][4][4];
#pragma unroll
        for (int mt = 0; mt < 2; mt++)
#pragma unroll
            for (int ks = 0; ks < 4; ks++) {
                uint32_t addr = abuf[cur] + (mt * 16 + (lane & 15)) * ASTRIDE_B + ks * 32 + (lane >> 4) * 16;
                LDMATRIX_X4(af[mt][ks][0], af[mt][ks][1], af[mt][ks][2], af[mt][ks][3], addr);
            }
#pragma unroll
        for (int mt = 0; mt < 2; mt++)
#pragma unroll
            for (int ks = 0; ks < 4; ks++) {
                ADD_BF16X2(af[mt][ks][0], af[mt][ks][0], qv[ks][0]); MAX_BF16X2(af[mt][ks][0], af[mt][ks][0], 0u);
                ADD_BF16X2(af[mt][ks][1], af[mt][ks][1], qv[ks][0]); MAX_BF16X2(af[mt][ks][1], af[mt][ks][1], 0u);
                ADD_BF16X2(af[mt][ks][2], af[mt][ks][2], qv[ks][1]); MAX_BF16X2(af[mt][ks][2], af[mt][ks][2], 0u);
                ADD_BF16X2(af[mt][ks][3], af[mt][ks][3], qv[ks][1]); MAX_BF16X2(af[mt][ks][3], af[mt][ks][3], 0u);
            }

        // ---- layer 2 (HMMA, B fully from registers) + layer 3 folded per n-tile ----
        float sp0 = 0.f, sp1 = 0.f, sp2 = 0.f, sp3 = 0.f;
#pragma unroll
        for (int nt = 0; nt < 8; nt++) {
            int j = nt * 8 + j0l;
            float bb0 = sb2[j], bb1 = sb2[j + 1];
            float w30 = sW3[j], w31 = sW3[j + 1];
#pragma unroll
            for (int mt = 0; mt < 2; mt++) {
                float d0 = bb0, d1 = bb1, d2 = bb0, d3 = bb1;
#pragma unroll
                for (int ks = 0; ks < 4; ks++)
                    MMA16816(d0, d1, d2, d3,
                             af[mt][ks][0], af[mt][ks][1], af[mt][ks][2], af[mt][ks][3],
                             bf[nt][ks][0], bf[nt][ks][1]);
                float lo = fmaf(fmaxf(d0, 0.f), w30, fmaf(fmaxf(d1, 0.f), w31, 0.f));
                float hi = fmaf(fmaxf(d2, 0.f), w30, fmaf(fmaxf(d3, 0.f), w31, 0.f));
                if (mt == 0) { sp0 += lo; sp1 += hi; } else { sp2 += lo; sp3 += hi; }
            }
        }
        sp0 += __shfl_xor_sync(0xffffffffu, sp0, 1); sp0 += __shfl_xor_sync(0xffffffffu, sp0, 2);
        sp1 += __shfl_xor_sync(0xffffffffu, sp1, 1); sp1 += __shfl_xor_sync(0xffffffffu, sp1, 2);
        sp2 += __shfl_xor_sync(0xffffffffu, sp2, 1); sp2 += __shfl_xor_sync(0xffffffffu, sp2, 2);
        sp3 += __shfl_xor_sync(0xffffffffu, sp3, 1); sp3 += __shfl_xor_sync(0xffffffffu, sp3, 2);
        int src = (lane & 7) * 4;
        float v0s = __shfl_sync(0xffffffffu, sp0, src);
        float v1s = __shfl_sync(0xffffffffu, sp1, src);
        float v2s = __shfl_sync(0xffffffffu, sp2, src);
        float v3s = __shfl_sync(0xffffffffu, sp3, src);
        float score = ((lane < 8) ? v0s : (lane < 16) ? v1s : (lane < 24) ? v2s : v3s) + b3f;

        // ---- masked softmax across warp (masked lanes -> att exactly 0) ----
        float sc = m ? score : -1e30f;
        float mx = sc;
#pragma unroll
        for (int o = 16; o; o >>= 1) mx = fmaxf(mx, __shfl_xor_sync(0xffffffffu, mx, o));
        float e = __expf(sc - mx);
        float sum = e;
#pragma unroll
        for (int o = 16; o; o >>= 1) sum += __shfl_xor_sync(0xffffffffu, sum, o);
        float att = __fdividef(e, sum);

        // ---- epilogue, cooperative: out[cols] = sum_r att_r * u2e[idx_r][cols] ----
        float a0 = 0.f, a1 = 0.f, a2 = 0.f, a3 = 0.f;
#pragma unroll
        for (int it = 0; it < 16; it++) {
            int row = it * 2 + erow_sub;
            float attr = __shfl_sync(0xffffffffu, att, row);
            int ridx = __shfl_sync(0xffffffffu, idx, row);
            float4 v = *(const float4*)(u2e + (size_t)ridx * D + ecol);
            a0 = fmaf(attr, v.x, a0);
            a1 = fmaf(attr, v.y, a1);
            a2 = fmaf(attr, v.z, a2);
            a3 = fmaf(attr, v.w, a3);
        }
        a0 += __shfl_xor_sync(0xffffffffu, a0, 16);
        a1 += __shfl_xor_sync(0xffffffffu, a1, 16);
        a2 += __shfl_xor_sync(0xffffffffu, a2, 16);
        a3 += __shfl_xor_sync(0xffffffffu, a3, 16);
        if (lane < 16)
            *(float4*)(out + (size_t)n * D + ecol) = make_float4(a0, a1, a2, a3);

        // ---- rotate pipeline state ----
        idx = idx2; m = m2; cur = nxt;
    }
    CP_WAIT0();   // drain the dangling prefetch before exit
}

// ======================= launch =======================
// Input order (metadata): u2e, W1, b1, W2, b2, W3, b3, nodes, neigh_idx, neigh_mask
extern "C" void kernel_launch(void* const* d_in, const int* in_sizes, int n_in,
                              void* d_out, int out_size) {
    const float* u2e = (const float*)d_in[0];
    const float* W1  = (const float*)d_in[1];
    const float* b1  = (const float*)d_in[2];
    const float* W2  = (const float*)d_in[3];
    const float* b2  = (const float*)d_in[4];
    const float* W3  = (const float*)d_in[5];
    const float* b3  = (const float*)d_in[6];
    const int*   nodes     = (const int*)d_in[7];
    const int*   neigh_idx = (const int*)d_in[8];
    const void*  neigh_mask = d_in[9];
    float* out = (float*)d_out;

    int V = in_sizes[0] / D;
    if (V > VOCAB_MAX) V = VOCAB_MAX;
    int n_nodes = in_sizes[7];
    int n_words = in_sizes[9] / 4;   // safe lower bound under both dtypes

    prep_mma_kernel<<<(V + 127) / 128, 128>>>(u2e, W1, b1, V,
                                              (const unsigned int*)neigh_mask, n_words);
    agg_mma_kernel<<<592, 128>>>(u2e, W2, b2, W3, b3,
                                 nodes, neigh_idx, neigh_mask, out, n_nodes);
}

// round 12
// speedup vs baseline: 1.1480x; 1.1480x over previous
#include <cuda_runtime.h>
#include <cuda_bf16.h>
#include <cstdint>

#define D 64
#define K 32
#define VOCAB_MAX 100000

// Scratch (alloc-free rule): bf16 P/Q
__device__ unsigned short g_Pb[(size_t)VOCAB_MAX * D];   // bf16(u2e @ W1a)
__device__ unsigned short g_Qb[(size_t)VOCAB_MAX * D];   // bf16(u2e @ W1b + b1)
__device__ int g_flags[1];   // [0] != 0 -> mask buffer is bytes (else 32-bit words)

// ======================= helpers =======================
__device__ __forceinline__ uint32_t smem_to_u32(const void* p) {
    uint32_t a;
    asm("{ .reg .u64 t; cvta.to.shared.u64 t, %1; cvt.u32.u64 %0, t; }" : "=r"(a) : "l"(p));
    return a;
}
#define CVT_BF16X2_F32(result, a, b) \
    asm("cvt.rn.satfinite.bf16x2.f32 %0, %1, %2;" : "=r"(result) : "f"(b), "f"(a))
#define ADD_BF16X2(r, a, b) \
    asm("add.bf16x2 %0, %1, %2;" : "=r"(r) : "r"(a), "r"(b))
#define MAX_BF16X2(r, a, b) \
    asm("max.bf16x2 %0, %1, %2;" : "=r"(r) : "r"(a), "r"(b))

#define LDMATRIX_X4(r0, r1, r2, r3, addr) \
    asm volatile("ldmatrix.sync.aligned.m8n8.x4.shared.b16 {%0,%1,%2,%3}, [%4];" \
        : "=r"(r0), "=r"(r1), "=r"(r2), "=r"(r3) : "r"(addr))
#define LDMATRIX_X4_TRANS(r0, r1, r2, r3, addr) \
    asm volatile("ldmatrix.sync.aligned.m8n8.x4.trans.shared.b16 {%0,%1,%2,%3}, [%4];" \
        : "=r"(r0), "=r"(r1), "=r"(r2), "=r"(r3) : "r"(addr))

// D (f32) += A (bf16) x B (bf16); C==D accumulate in place
#define MMA16816(d0, d1, d2, d3, a0, a1, a2, a3, b0, b1) \
    asm volatile("mma.sync.aligned.m16n8k16.row.col.f32.bf16.bf16.f32 " \
        "{%0,%1,%2,%3}, {%4,%5,%6,%7}, {%8,%9}, {%0,%1,%2,%3};" \
        : "+f"(d0), "+f"(d1), "+f"(d2), "+f"(d3) \
        : "r"(a0), "r"(a1), "r"(a2), "r"(a3), "r"(b0), "r"(b1))

// A-tile SMEM: row stride 72 bf16 (144B) -> conflict-free ldmatrix
#define ASTRIDE_B 144

// ======================= prep: P/Q (bf16 out) + mask dtype scan =======================
__global__ __launch_bounds__(128) void prep_mma_kernel(const float* __restrict__ u2e,
                                                       const float* __restrict__ W1,
                                                       const float* __restrict__ b1,
                                                       int V,
                                                       const unsigned int* __restrict__ mbuf,
                                                       int n_words) {
    __shared__ __align__(16) unsigned char sA[4][32 * ASTRIDE_B];
    __shared__ __align__(16) unsigned char sW[128 * ASTRIDE_B];  // W1 [128 k][64 n] bf16
    __shared__ float sb1[64];
    int tid = threadIdx.x, warp = tid >> 5, lane = tid & 31;

    // ---- mask dtype scan (byte vs word); 0->1 idempotent across graph replays ----
    {
        int byte_mode = 0;
        for (int i = blockIdx.x * blockDim.x + tid; i < n_words; i += gridDim.x * blockDim.x) {
            unsigned int w = mbuf[i];
            if (w != 0u && w != 1u && w != 0x3f800000u) { byte_mode = 1; break; }
        }
        if (byte_mode) atomicOr(&g_flags[0], 1);
    }

    // ---- stage W1 (bf16, padded rows) ----
    for (int p = tid; p < 128 * 32; p += 128) {
        int r = p >> 5, cp = p & 31;
        uint32_t v;
        CVT_BF16X2_F32(v, W1[(size_t)r * 64 + 2 * cp], W1[(size_t)r * 64 + 2 * cp + 1]);
        *(uint32_t*)(sW + r * ASTRIDE_B + cp * 4) = v;
    }
    if (tid < 64) sb1[tid] = b1[tid];
    __syncthreads();

    int v0 = (blockIdx.x * 4 + warp) * 32;
    int vr = v0 + lane;
    int vc = (vr < V) ? vr : (V - 1);

    // Stage this lane's u2e row as bf16 into the warp's A tile
    {
        const float4* row = (const float4*)(u2e + (size_t)vc * D);
        unsigned char* dst = sA[warp] + lane * ASTRIDE_B;
#pragma unroll
        for (int i = 0; i < 8; i++) {
            float4 f0 = row[2 * i], f1 = row[2 * i + 1];
            uint4 w;
            CVT_BF16X2_F32(w.x, f0.x, f0.y);
            CVT_BF16X2_F32(w.y, f0.z, f0.w);
            CVT_BF16X2_F32(w.z, f1.x, f1.y);
            CVT_BF16X2_F32(w.w, f1.z, f1.w);
            *(uint4*)(dst + i * 16) = w;
        }
    }
    __syncwarp();

    uint32_t af[2][4][4];
    uint32_t a_base = smem_to_u32(sA[warp]);
#pragma unroll
    for (int mt = 0; mt < 2; mt++)
#pragma unroll
        for (int ks = 0; ks < 4; ks++) {
            uint32_t addr = a_base + (mt * 16 + (lane & 15)) * ASTRIDE_B + ks * 32 + (lane >> 4) * 16;
            LDMATRIX_X4(af[mt][ks][0], af[mt][ks][1], af[mt][ks][2], af[mt][ks][3], addr);
        }

    uint32_t w_base = smem_to_u32(sW);
    int j0 = 2 * (lane & 3);
    int r0 = lane >> 2;

#pragma unroll
    for (int half = 0; half < 2; half++) {
        unsigned short* gOut = half ? g_Qb : g_Pb;
#pragma unroll
        for (int nt = 0; nt < 8; nt++) {
            uint32_t b[4][2];
            {
                uint32_t r0b, r1b, r2b, r3b;
                uint32_t addr = w_base + (half * 64 + lane) * ASTRIDE_B + nt * 16;
                LDMATRIX_X4_TRANS(r0b, r1b, r2b, r3b, addr);
                b[0][0] = r0b; b[0][1] = r1b; b[1][0] = r2b; b[1][1] = r3b;
                addr = w_base + (half * 64 + 32 + lane) * ASTRIDE_B + nt * 16;
                LDMATRIX_X4_TRANS(r0b, r1b, r2b, r3b, addr);
                b[2][0] = r0b; b[2][1] = r1b; b[3][0] = r2b; b[3][1] = r3b;
            }
            int j = nt * 8 + j0;
            float init0 = half ? sb1[j] : 0.f;
            float init1 = half ? sb1[j + 1] : 0.f;
#pragma unroll
            for (int mt = 0; mt < 2; mt++) {
                float d0 = init0, d1 = init1, d2 = init0, d3 = init1;
#pragma unroll
                for (int ks = 0; ks < 4; ks++)
                    MMA16816(d0, d1, d2, d3,
                             af[mt][ks][0], af[mt][ks][1], af[mt][ks][2], af[mt][ks][3],
                             b[ks][0], b[ks][1]);
                int ra = v0 + mt * 16 + r0;
                int rb = ra + 8;
                uint32_t wlo, whi;
                CVT_BF16X2_F32(wlo, d0, d1);
                CVT_BF16X2_F32(whi, d2, d3);
                if (ra < V) *(uint32_t*)(gOut + (size_t)ra * D + j) = wlo;
                if (rb < V) *(uint32_t*)(gOut + (size_t)rb * D + j) = whi;
            }
        }
    }
}

// ======================= agg: persistent; software-pipelined gathers ====================
// R10 structure (best known): B fragments half-hoisted, next node's P rows prefetched
// into registers. New: first half of epilogue E loads issued before softmax section.
__global__ __launch_bounds__(256, 2) void agg_mma_kernel(
    const float* __restrict__ u2e,
    const float* __restrict__ W2, const float* __restrict__ b2,
    const float* __restrict__ W3, const float* __restrict__ b3,
    const int* __restrict__ nodes, const int* __restrict__ neigh_idx,
    const void* __restrict__ maskbuf,
    float* __restrict__ out, int n_nodes) {
    __shared__ __align__(16) unsigned char sA[8][32 * ASTRIDE_B];  // per-warp h1 tiles
    __shared__ __align__(16) unsigned char sW2[64 * ASTRIDE_B];    // W2 staging (bf16)
    __shared__ float sb2[64];
    __shared__ float sW3[64];
    int tid = threadIdx.x, warp = tid >> 5, lane = tid & 31;

    for (int p = tid; p < 64 * 32; p += 256) {
        int r = p >> 5, cp = p & 31;
        uint32_t v;
        CVT_BF16X2_F32(v, W2[(size_t)r * 64 + 2 * cp], W2[(size_t)r * 64 + 2 * cp + 1]);
        *(uint32_t*)(sW2 + r * ASTRIDE_B + cp * 4) = v;
    }
    if (tid < 64) { sb2[tid] = b2[tid]; sW3[tid] = W3[tid]; }
    __syncthreads();

    uint32_t w_base = smem_to_u32(sW2);

    // ---- hoist B fragments for n-tiles 0..3 only (register budget) ----
    uint32_t bfh[4][4][2];
#pragma unroll
    for (int nt = 0; nt < 4; nt++) {
        uint32_t r0b, r1b, r2b, r3b;
        uint32_t addr = w_base + lane * ASTRIDE_B + nt * 16;
        LDMATRIX_X4_TRANS(r0b, r1b, r2b, r3b, addr);
        bfh[nt][0][0] = r0b; bfh[nt][0][1] = r1b; bfh[nt][1][0] = r2b; bfh[nt][1][1] = r3b;
        addr = w_base + (32 + lane) * ASTRIDE_B + nt * 16;
        LDMATRIX_X4_TRANS(r0b, r1b, r2b, r3b, addr);
        bfh[nt][2][0] = r0b; bfh[nt][2][1] = r1b; bfh[nt][3][0] = r2b; bfh[nt][3][1] = r3b;
    }

    const float b3f = b3[0];
    const int byte_mode = g_flags[0];
    uint32_t a_base = smem_to_u32(sA[warp]);
    const int j0l = 2 * (lane & 3);
    const int seg = lane & 7;        // 16B segment within a 128B bf16 row
    const int rsub = lane >> 3;      // 0..3 (row within a 4-row load group)
    const int erow_sub = lane >> 4;  // 0..1 (row parity for epilogue)
    const int ecol = (lane & 15) * 4;
    int wg = blockIdx.x * 8 + warp;
    int stride = gridDim.x * 8;

    if (wg >= n_nodes) return;

    // ---- pipeline prologue: front-end for the first node ----
    int idx, m;
    uint4 q4, p4[8];
    {
        int node = nodes[wg];
        idx = neigh_idx[wg * K + lane];
        if (byte_mode)
            m = ((const unsigned char*)maskbuf)[(size_t)wg * K + lane] != 0;
        else
            m = ((const unsigned int*)maskbuf)[(size_t)wg * K + lane] != 0u;
        q4 = *(const uint4*)(g_Qb + (size_t)node * D + seg * 8);
#pragma unroll
        for (int it = 0; it < 8; it++) {
            int ridx = __shfl_sync(0xffffffffu, idx, it * 4 + rsub);
            p4[it] = *(const uint4*)(g_Pb + (size_t)ridx * D + seg * 8);
        }
    }

    for (int n = wg; n < n_nodes; n += stride) {
        // ---- layer 1: consume prefetched P/Q -> relu -> A tile ----
        {
            unsigned char* aw = sA[warp];
#pragma unroll
            for (int it = 0; it < 8; it++) {
                uint4 w;
                ADD_BF16X2(w.x, p4[it].x, q4.x); MAX_BF16X2(w.x, w.x, 0u);
                ADD_BF16X2(w.y, p4[it].y, q4.y); MAX_BF16X2(w.y, w.y, 0u);
                ADD_BF16X2(w.z, p4[it].z, q4.z); MAX_BF16X2(w.z, w.z, 0u);
                ADD_BF16X2(w.w, p4[it].w, q4.w); MAX_BF16X2(w.w, w.w, 0u);
                *(uint4*)(aw + (it * 4 + rsub) * ASTRIDE_B + seg * 16) = w;
            }
        }
        __syncwarp();

        // ---- prefetch next node's front-end (overlaps MMA/softmax/epilogue) ----
        int n2 = n + stride;
        int nc2 = (n2 < n_nodes) ? n2 : n;
        int idx2 = neigh_idx[(size_t)nc2 * K + lane];
        int m2;
        if (byte_mode)
            m2 = ((const unsigned char*)maskbuf)[(size_t)nc2 * K + lane] != 0;
        else
            m2 = ((const unsigned int*)maskbuf)[(size_t)nc2 * K + lane] != 0u;
        int node2 = nodes[nc2];
        uint4 q42 = *(const uint4*)(g_Qb + (size_t)node2 * D + seg * 8);
        uint4 p42[8];
#pragma unroll
        for (int it = 0; it < 8; it++) {
            int ridx = __shfl_sync(0xffffffffu, idx2, it * 4 + rsub);
            p42[it] = *(const uint4*)(g_Pb + (size_t)ridx * D + seg * 8);
        }

        // ---- A fragments (2 m-tiles x 4 k-steps) ----
        uint32_t af[2][4][4];
#pragma unroll
        for (int mt = 0; mt < 2; mt++)
#pragma unroll
            for (int ks = 0; ks < 4; ks++) {
                uint32_t addr = a_base + (mt * 16 + (lane & 15)) * ASTRIDE_B + ks * 32 + (lane >> 4) * 16;
                LDMATRIX_X4(af[mt][ks][0], af[mt][ks][1], af[mt][ks][2], af[mt][ks][3], addr);
            }

        // ---- layer 2 (HMMA) + layer 3 folded per n-tile ----
        float sp0 = 0.f, sp1 = 0.f, sp2 = 0.f, sp3 = 0.f;
#pragma unroll
        for (int nt = 0; nt < 8; nt++) {
            uint32_t b[4][2];
            if (nt < 4) {
#pragma unroll
                for (int ks = 0; ks < 4; ks++) { b[ks][0] = bfh[nt][ks][0]; b[ks][1] = bfh[nt][ks][1]; }
            } else {
                uint32_t r0b, r1b, r2b, r3b;
                uint32_t addr = w_base + lane * ASTRIDE_B + nt * 16;
                LDMATRIX_X4_TRANS(r0b, r1b, r2b, r3b, addr);
                b[0][0] = r0b; b[0][1] = r1b; b[1][0] = r2b; b[1][1] = r3b;
                addr = w_base + (32 + lane) * ASTRIDE_B + nt * 16;
                LDMATRIX_X4_TRANS(r0b, r1b, r2b, r3b, addr);
                b[2][0] = r0b; b[2][1] = r1b; b[3][0] = r2b; b[3][1] = r3b;
            }
            int j = nt * 8 + j0l;
            float bb0 = sb2[j], bb1 = sb2[j + 1];
            float w30 = sW3[j], w31 = sW3[j + 1];
#pragma unroll
            for (int mt = 0; mt < 2; mt++) {
                float d0 = bb0, d1 = bb1, d2 = bb0, d3 = bb1;
#pragma unroll
                for (int ks = 0; ks < 4; ks++)
                    MMA16816(d0, d1, d2, d3,
                             af[mt][ks][0], af[mt][ks][1], af[mt][ks][2], af[mt][ks][3],
                             b[ks][0], b[ks][1]);
                float lo = fmaf(fmaxf(d0, 0.f), w30, fmaf(fmaxf(d1, 0.f), w31, 0.f));
                float hi = fmaf(fmaxf(d2, 0.f), w30, fmaf(fmaxf(d3, 0.f), w31, 0.f));
                if (mt == 0) { sp0 += lo; sp1 += hi; } else { sp2 += lo; sp3 += hi; }
            }
        }

        // ---- early-issue first half of epilogue E gather (depends only on idx) ----
        // af is dead here; ev(32 regs) overlaps the shuffle/softmax section below.
        float4 ev[8];
#pragma unroll
        for (int it = 0; it < 8; it++) {
            int row = it * 2 + erow_sub;
            int ridx = __shfl_sync(0xffffffffu, idx, row);
            ev[it] = *(const float4*)(u2e + (size_t)ridx * D + ecol);
        }

        // ---- score reduction across lanes ----
        sp0 += __shfl_xor_sync(0xffffffffu, sp0, 1); sp0 += __shfl_xor_sync(0xffffffffu, sp0, 2);
        sp1 += __shfl_xor_sync(0xffffffffu, sp1, 1); sp1 += __shfl_xor_sync(0xffffffffu, sp1, 2);
        sp2 += __shfl_xor_sync(0xffffffffu, sp2, 1); sp2 += __shfl_xor_sync(0xffffffffu, sp2, 2);
        sp3 += __shfl_xor_sync(0xffffffffu, sp3, 1); sp3 += __shfl_xor_sync(0xffffffffu, sp3, 2);
        int src = (lane & 7) * 4;
        float v0s = __shfl_sync(0xffffffffu, sp0, src);
        float v1s = __shfl_sync(0xffffffffu, sp1, src);
        float v2s = __shfl_sync(0xffffffffu, sp2, src);
        float v3s = __shfl_sync(0xffffffffu, sp3, src);
        float score = ((lane < 8) ? v0s : (lane < 16) ? v1s : (lane < 24) ? v2s : v3s) + b3f;

        // ---- masked softmax across warp (masked lanes -> att exactly 0) ----
        float sc = m ? score : -1e30f;
        float mx = sc;
#pragma unroll
        for (int o = 16; o; o >>= 1) mx = fmaxf(mx, __shfl_xor_sync(0xffffffffu, mx, o));
        float e = __expf(sc - mx);
        float sum = e;
#pragma unroll
        for (int o = 16; o; o >>= 1) sum += __shfl_xor_sync(0xffffffffu, sum, o);
        float att = __fdividef(e, sum);

        // ---- epilogue: consume prefetched rows 0..15, then gather rows 16..31 ----
        float a0 = 0.f, a1 = 0.f, a2 = 0.f, a3 = 0.f;
#pragma unroll
        for (int it = 0; it < 8; it++) {
            float attr = __shfl_sync(0xffffffffu, att, it * 2 + erow_sub);
            a0 = fmaf(attr, ev[it].x, a0);
            a1 = fmaf(attr, ev[it].y, a1);
            a2 = fmaf(attr, ev[it].z, a2);
            a3 = fmaf(attr, ev[it].w, a3);
        }
#pragma unroll
        for (int it = 8; it < 16; it++) {
            int row = it * 2 + erow_sub;
            float attr = __shfl_sync(0xffffffffu, att, row);
            int ridx = __shfl_sync(0xffffffffu, idx, row);
            float4 v = *(const float4*)(u2e + (size_t)ridx * D + ecol);
            a0 = fmaf(attr, v.x, a0);
            a1 = fmaf(attr, v.y, a1);
            a2 = fmaf(attr, v.z, a2);
            a3 = fmaf(attr, v.w, a3);
        }
        a0 += __shfl_xor_sync(0xffffffffu, a0, 16);
        a1 += __shfl_xor_sync(0xffffffffu, a1, 16);
        a2 += __shfl_xor_sync(0xffffffffu, a2, 16);
        a3 += __shfl_xor_sync(0xffffffffu, a3, 16);
        if (lane < 16)
            *(float4*)(out + (size_t)n * D + ecol) = make_float4(a0, a1, a2, a3);

        // ---- rotate pipeline registers ----
        idx = idx2; m = m2; q4 = q42;
#pragma unroll
        for (int it = 0; it < 8; it++) p4[it] = p42[it];
    }
}

// ======================= launch =======================
// Input order (metadata): u2e, W1, b1, W2, b2, W3, b3, nodes, neigh_idx, neigh_mask
extern "C" void kernel_launch(void* const* d_in, const int* in_sizes, int n_in,
                              void* d_out, int out_size) {
    const float* u2e = (const float*)d_in[0];
    const float* W1  = (const float*)d_in[1];
    const float* b1  = (const float*)d_in[2];
    const float* W2  = (const float*)d_in[3];
    const float* b2  = (const float*)d_in[4];
    const float* W3  = (const float*)d_in[5];
    const float* b3  = (const float*)d_in[6];
    const int*   nodes     = (const int*)d_in[7];
    const int*   neigh_idx = (const int*)d_in[8];
    const void*  neigh_mask = d_in[9];
    float* out = (float*)d_out;

    int V = in_sizes[0] / D;
    if (V > VOCAB_MAX) V = VOCAB_MAX;
    int n_nodes = in_sizes[7];
    int n_words = in_sizes[9] / 4;   // safe lower bound under both dtypes

    prep_mma_kernel<<<(V + 127) / 128, 128>>>(u2e, W1, b1, V,
                                              (const unsigned int*)neigh_mask, n_words);
    agg_mma_kernel<<<296, 256>>>(u2e, W2, b2, W3, b3,
                                 nodes, neigh_idx, neigh_mask, out, n_nodes);
}